// round 4
// baseline (speedup 1.0000x reference)
#include <cuda_runtime.h>

// LightGCN on GB300 (sm_103a).
// Pipeline per call (graph-capturable, deterministic):
//   1. k_count     : in-degree over dst (atomics)  [degi statically/tail zeroed]
//   2. k_scan      : single-pass decoupled-lookback exclusive scan -> ptr/cursor/degf
//   3. k_scatter   : counting-sort edges into dst buckets, packed (src,norm) float2
//   4. k_prop0     : layer 1, gathers x0 virtually from user_emb/item_emb,
//                    writes out = 0.25*(x0 + x1) (pure store)
//   5. k_prop      : layer 2 (g_xb -> g_xa), out += 0.25*x2
//   6. k_prop      : layer 3 (g_xa -> g_xb), out += 0.25*x3
//   7. k_tail      : re-zero degi + lookback flags for the next call
// edge_index arrives as int32 (JAX x64 disabled downgrades jnp.int64).

#define D       32
#define NMAX    300032
#define EMAX    5000064
#define SCAN_B  1024
#define NBMAX   512          // max scan blocks (300032/1024 = 293)

__device__ float  g_xa[NMAX * D];
__device__ float  g_xb[NMAX * D];
__device__ int    g_degi[NMAX];          // statically zero; re-zeroed by k_tail
__device__ float  g_degf[NMAX];
__device__ int    g_ptr[NMAX + 1];
__device__ int    g_cursor[NMAX];
__device__ float2 g_edge[EMAX];          // .x = src (int bits), .y = norm
__device__ volatile int g_agg[NBMAX];
__device__ volatile int g_incl[NBMAX];
__device__ volatile int g_flag[NBMAX];   // 0=none, 1=aggregate, 2=inclusive; tail-zeroed

// ---- 1. in-degree over dst ------------------------------------------------
__global__ void k_count(const int* __restrict__ ei, int E) {
    int e = blockIdx.x * blockDim.x + threadIdx.x;
    if (e < E) {
        int dd = ei[E + e];
        if (dd >= 0 && dd < NMAX) atomicAdd(&g_degi[dd], 1);
    }
}

// ---- 2. single-pass scan (decoupled lookback) ------------------------------
__global__ void k_scan(int n, int E) {
    __shared__ int sh[SCAN_B];
    __shared__ int sh_prefix;
    int b   = blockIdx.x;
    int tid = threadIdx.x;
    int gid = b * SCAN_B + tid;
    int v = (gid < n) ? g_degi[gid] : 0;
    sh[tid] = v;
    __syncthreads();
    for (int off = 1; off < SCAN_B; off <<= 1) {
        int t = (tid >= off) ? sh[tid - off] : 0;
        __syncthreads();
        sh[tid] += t;
        __syncthreads();
    }
    int total = sh[SCAN_B - 1];

    if (tid == 0) {
        g_agg[b] = total;
        __threadfence();
        g_flag[b] = 1;
        // lookback
        int sum = 0;
        for (int j = b - 1; j >= 0; --j) {
            int f;
            do { f = g_flag[j]; } while (f == 0);
            if (f == 2) { sum += g_incl[j]; break; }
            sum += g_agg[j];
        }
        sh_prefix = sum;
        g_incl[b] = sum + total;
        __threadfence();
        g_flag[b] = 2;
    }
    __syncthreads();

    int excl = sh_prefix + sh[tid] - v;       // exclusive prefix
    if (gid < n) {
        g_ptr[gid]    = excl;
        g_cursor[gid] = excl;
        g_degf[gid]   = (float)g_degi[gid];
    } else if (gid == n) {
        g_ptr[n] = E;
    }
}

// ---- 3. counting-sort scatter: one 8B (src, norm) store per edge ----------
__global__ void k_scatter(const int* __restrict__ ei, int E) {
    int e = blockIdx.x * blockDim.x + threadIdx.x;
    if (e >= E) return;
    int s  = ei[e];
    int dd = ei[E + e];
    if (s < 0 || s >= NMAX || dd < 0 || dd >= NMAX) return;
    int pos = atomicAdd(&g_cursor[dd], 1);
    float dp = g_degf[s] * g_degf[dd];
    float nm = (dp > 0.f) ? rsqrtf(dp) : 0.f;
    g_edge[pos] = make_float2(__int_as_float(s), nm);
}

// ---- 4. layer 1: virtual x0 gather, out = 0.25*(x0 + x1) -------------------
__global__ void k_prop0(const float* __restrict__ ue, const float* __restrict__ ie,
                        float* __restrict__ out, int n_users, int n) {
    int w    = (blockIdx.x * blockDim.x + threadIdx.x) >> 5;
    int lane = threadIdx.x & 31;
    if (w >= n) return;
    int i = g_ptr[w], end = g_ptr[w + 1];
    float a = 0.f;
    for (; i + 8 <= end; i += 8) {
        float2 e[8];
        #pragma unroll
        for (int k = 0; k < 8; ++k) e[k] = g_edge[i + k];
        #pragma unroll
        for (int k = 0; k < 8; ++k) {
            int s = __float_as_int(e[k].x);
            const float* base = (s < n_users) ? (ue + s * D)
                                              : (ie + (s - n_users) * D);
            a = fmaf(base[lane], e[k].y, a);
        }
    }
    for (; i < end; ++i) {
        float2 ee = g_edge[i];
        int s = __float_as_int(ee.x);
        const float* base = (s < n_users) ? (ue + s * D)
                                          : (ie + (s - n_users) * D);
        a = fmaf(base[lane], ee.y, a);
    }
    // own x0 row
    float x0 = (w < n_users) ? ue[w * D + lane] : ie[(w - n_users) * D + lane];
    int o = w * D + lane;
    g_xb[o] = a;                       // x1
    out[o]  = 0.25f * (x0 + a);        // pure store, no RMW
}

// ---- 5/6. layers 2,3: warp per dst node, out += 0.25 * x_new ---------------
__global__ void k_prop(int sel, float* __restrict__ out, int n) {
    int w    = (blockIdx.x * blockDim.x + threadIdx.x) >> 5;
    int lane = threadIdx.x & 31;
    if (w >= n) return;
    const float* __restrict__ xin  = sel ? g_xa : g_xb;
    float*       __restrict__ xout = sel ? g_xb : g_xa;
    int i = g_ptr[w], end = g_ptr[w + 1];
    float a = 0.f;
    for (; i + 8 <= end; i += 8) {
        float2 e[8];
        #pragma unroll
        for (int k = 0; k < 8; ++k) e[k] = g_edge[i + k];
        #pragma unroll
        for (int k = 0; k < 8; ++k)
            a = fmaf(xin[__float_as_int(e[k].x) * D + lane], e[k].y, a);
    }
    for (; i < end; ++i) {
        float2 ee = g_edge[i];
        a = fmaf(xin[__float_as_int(ee.x) * D + lane], ee.y, a);
    }
    int o = w * D + lane;
    xout[o] = a;
    out[o] += 0.25f * a;
}

// ---- 7. reset accumulated state for the next call --------------------------
__global__ void k_tail(int n) {
    int i = blockIdx.x * blockDim.x + threadIdx.x;
    if (i < n) g_degi[i] = 0;
    if (i < NBMAX) g_flag[i] = 0;
}

extern "C" void kernel_launch(void* const* d_in, const int* in_sizes, int n_in,
                              void* d_out, int out_size) {
    const int* ei = (const int*)d_in[0];   // edge_index: int32
    int iu = (n_in >= 5) ? 3 : 1;
    const float* ue = (const float*)d_in[iu];
    const float* ie = (const float*)d_in[iu + 1];
    int E       = in_sizes[0] / 2;
    int n_users = in_sizes[iu] / D;
    int n_items = in_sizes[iu + 1] / D;
    int n = n_users + n_items;
    float* out = (float*)d_out;

    const int TB = 256;
    int nb = (n + SCAN_B - 1) / SCAN_B;        // ~293 <= NBMAX

    k_count  <<<(E + TB - 1) / TB, TB>>>(ei, E);
    k_scan   <<<nb, SCAN_B>>>(n, E);
    k_scatter<<<(E + TB - 1) / TB, TB>>>(ei, E);

    int gp = (n * 32 + TB - 1) / TB;           // one warp per node
    k_prop0<<<gp, TB>>>(ue, ie, out, n_users, n);   // launch #4 -> ncu slot
    k_prop <<<gp, TB>>>(0, out, n);                 // x1(g_xb) -> x2(g_xa)
    k_prop <<<gp, TB>>>(1, out, n);                 // x2(g_xa) -> x3(g_xb)

    k_tail<<<(n + TB - 1) / TB, TB>>>(n);
}

// round 5
// speedup vs baseline: 1.0697x; 1.0697x over previous
#include <cuda_runtime.h>

// LightGCN on GB300 (sm_103a).
// Per call (graph-capturable, deterministic):
//   1. k_count_init : in-degree over dst (float atomics) + stream x0 into g_xa,
//                     out = 0.25*x0   (one grid covers both jobs)
//   2. k_scan       : single-pass decoupled-lookback exclusive scan -> ptr/cursor
//   3. k_scatter    : counting-sort edges into dst buckets, packed (src,norm) float2
//   4-6. k_prop x3  : warp per dst node; slot/chunk float4 layout:
//                     lane = (slot=lane>>3 edge slot, chunk=lane&7 float4 of row).
//                     4 edges per gather instruction, 8 in flight; shfl.xor reduce.
//                     out += 0.25*x_l; layer 3 skips the x store.
//   7. k_tail       : re-zero degf + lookback flags for the next call
// edge_index arrives as int32 (JAX x64 disabled downgrades jnp.int64).

#define D       32
#define NMAX    300032
#define EMAX    5000064
#define SCAN_B  1024
#define NBMAX   512

__device__ float  g_xa[NMAX * D];
__device__ float  g_xb[NMAX * D];
__device__ float  g_degf[NMAX];          // statically zero; re-zeroed by k_tail
__device__ int    g_ptr[NMAX + 1];
__device__ int    g_cursor[NMAX];
__device__ float2 g_edge[EMAX];          // .x = src (int bits), .y = norm
__device__ volatile int g_agg[NBMAX];
__device__ volatile int g_incl[NBMAX];
__device__ volatile int g_flag[NBMAX];   // 0/1/2; tail-zeroed

// ---- 1. degree count + x0 init (merged) ------------------------------------
__global__ void k_count_init(const int* __restrict__ ei, int E,
                             const float4* __restrict__ ue4,
                             const float4* __restrict__ ie4,
                             float4* __restrict__ out4,
                             int nu8, int total8) {
    int t = blockIdx.x * blockDim.x + threadIdx.x;
    if (t < E) {
        int dd = ei[E + t];
        if (dd >= 0 && dd < NMAX) atomicAdd(&g_degf[dd], 1.0f);
    }
    if (t < total8) {
        float4 v = (t < nu8) ? ue4[t] : ie4[t - nu8];
        ((float4*)g_xa)[t] = v;
        out4[t] = make_float4(0.25f * v.x, 0.25f * v.y, 0.25f * v.z, 0.25f * v.w);
    }
}

// ---- 2. single-pass scan (decoupled lookback) -------------------------------
__global__ void k_scan(int n, int E) {
    __shared__ int sh[SCAN_B];
    __shared__ int sh_prefix;
    int b = blockIdx.x, tid = threadIdx.x;
    int gid = b * SCAN_B + tid;
    int v = (gid < n) ? (int)g_degf[gid] : 0;
    sh[tid] = v;
    __syncthreads();
    for (int off = 1; off < SCAN_B; off <<= 1) {
        int t = (tid >= off) ? sh[tid - off] : 0;
        __syncthreads();
        sh[tid] += t;
        __syncthreads();
    }
    int total = sh[SCAN_B - 1];
    if (tid == 0) {
        g_agg[b] = total;
        __threadfence();
        g_flag[b] = 1;
        int sum = 0;
        for (int j = b - 1; j >= 0; --j) {
            int f;
            do { f = g_flag[j]; } while (f == 0);
            if (f == 2) { sum += g_incl[j]; break; }
            sum += g_agg[j];
        }
        sh_prefix = sum;
        g_incl[b] = sum + total;
        __threadfence();
        g_flag[b] = 2;
    }
    __syncthreads();
    int excl = sh_prefix + sh[tid] - v;
    if (gid < n) {
        g_ptr[gid]    = excl;
        g_cursor[gid] = excl;
    } else if (gid == n) {
        g_ptr[n] = E;
    }
}

// ---- 3. counting-sort scatter: one 8B (src, norm) store per edge -----------
__global__ void k_scatter(const int* __restrict__ ei, int E) {
    int e = blockIdx.x * blockDim.x + threadIdx.x;
    if (e >= E) return;
    int s  = ei[e];
    int dd = ei[E + e];
    if (s < 0 || s >= NMAX || dd < 0 || dd >= NMAX) return;
    int pos = atomicAdd(&g_cursor[dd], 1);
    float dp = g_degf[s] * g_degf[dd];
    float nm = (dp > 0.f) ? rsqrtf(dp) : 0.f;
    g_edge[pos] = make_float2(__int_as_float(s), nm);
}

// ---- 4-6. propagate layer: slot/chunk float4 layout -------------------------
// sel: 0 = g_xa->g_xb, 1 = g_xb->g_xa, 2 = g_xa->(no store, last layer)
__global__ void k_prop(int sel, float4* __restrict__ out4, int n) {
    int gw = (blockIdx.x * blockDim.x + threadIdx.x) >> 5;
    if (gw >= n) return;
    int lane  = threadIdx.x & 31;
    int chunk = lane & 7;        // which float4 of the 32-float row
    int slot  = lane >> 3;       // which of 4 concurrent edges
    const float4* __restrict__ xin  = (const float4*)(sel == 1 ? g_xb : g_xa);
    float4*       __restrict__ xout = (float4*)(sel == 1 ? g_xa : g_xb);
    int i0 = g_ptr[gw], end = g_ptr[gw + 1];

    float ax = 0.f, ay = 0.f, az = 0.f, aw = 0.f;
    float bx = 0.f, by = 0.f, bz = 0.f, bw = 0.f;
    int j = i0 + slot;
    for (; j + 4 < end; j += 8) {           // 8 edges per warp-iteration
        float2 e0 = g_edge[j];
        float2 e1 = g_edge[j + 4];
        float4 v0 = xin[__float_as_int(e0.x) * 8 + chunk];
        float4 v1 = xin[__float_as_int(e1.x) * 8 + chunk];
        ax = fmaf(v0.x, e0.y, ax); ay = fmaf(v0.y, e0.y, ay);
        az = fmaf(v0.z, e0.y, az); aw = fmaf(v0.w, e0.y, aw);
        bx = fmaf(v1.x, e1.y, bx); by = fmaf(v1.y, e1.y, by);
        bz = fmaf(v1.z, e1.y, bz); bw = fmaf(v1.w, e1.y, bw);
    }
    if (j < end) {
        float2 e0 = g_edge[j];
        float4 v0 = xin[__float_as_int(e0.x) * 8 + chunk];
        ax = fmaf(v0.x, e0.y, ax); ay = fmaf(v0.y, e0.y, ay);
        az = fmaf(v0.z, e0.y, az); aw = fmaf(v0.w, e0.y, aw);
    }
    ax += bx; ay += by; az += bz; aw += bw;
    // sum the 4 edge slots (chunk bits preserved by xor 8/16)
    ax += __shfl_xor_sync(0xffffffffu, ax, 8);
    ay += __shfl_xor_sync(0xffffffffu, ay, 8);
    az += __shfl_xor_sync(0xffffffffu, az, 8);
    aw += __shfl_xor_sync(0xffffffffu, aw, 8);
    ax += __shfl_xor_sync(0xffffffffu, ax, 16);
    ay += __shfl_xor_sync(0xffffffffu, ay, 16);
    az += __shfl_xor_sync(0xffffffffu, az, 16);
    aw += __shfl_xor_sync(0xffffffffu, aw, 16);

    int o = gw * 8 + chunk;
    if (slot == 0 && sel != 2)
        xout[o] = make_float4(ax, ay, az, aw);
    if (slot == 1) {                         // parallel with the xout store
        float4 c = out4[o];
        out4[o] = make_float4(c.x + 0.25f * ax, c.y + 0.25f * ay,
                              c.z + 0.25f * az, c.w + 0.25f * aw);
    }
}

// ---- 7. reset state for the next call ---------------------------------------
__global__ void k_tail(int n) {
    int i = blockIdx.x * blockDim.x + threadIdx.x;
    if (i < n) g_degf[i] = 0.f;
    if (i < NBMAX) g_flag[i] = 0;
}

extern "C" void kernel_launch(void* const* d_in, const int* in_sizes, int n_in,
                              void* d_out, int out_size) {
    const int* ei = (const int*)d_in[0];   // edge_index: int32
    int iu = (n_in >= 5) ? 3 : 1;
    const float* ue = (const float*)d_in[iu];
    const float* ie = (const float*)d_in[iu + 1];
    int E       = in_sizes[0] / 2;
    int n_users = in_sizes[iu] / D;
    int n_items = in_sizes[iu + 1] / D;
    int n = n_users + n_items;
    float4* out4 = (float4*)d_out;

    const int TB = 256;
    int nu8 = n_users * (D / 4);
    int total8 = n * (D / 4);
    int gc = max(E, total8);

    k_count_init<<<(gc + TB - 1) / TB, TB>>>(ei, E, (const float4*)ue,
                                             (const float4*)ie, out4, nu8, total8);
    int nb = (n + SCAN_B - 1) / SCAN_B;
    k_scan   <<<nb, SCAN_B>>>(n, E);
    k_scatter<<<(E + TB - 1) / TB, TB>>>(ei, E);

    int gp = (n * 32 + TB - 1) / TB;           // one warp per node
    k_prop<<<gp, TB>>>(0, out4, n);            // x0(g_xa) -> x1(g_xb)   [ncu slot]
    k_prop<<<gp, TB>>>(1, out4, n);            // x1(g_xb) -> x2(g_xa)
    k_prop<<<gp, TB>>>(2, out4, n);            // x2(g_xa) -> out only

    k_tail<<<(n + TB - 1) / TB, TB>>>(n);
}

// round 7
// speedup vs baseline: 1.4920x; 1.3948x over previous
#include <cuda_runtime.h>

// LightGCN on GB300 (sm_103a).
// Per call (graph-capturable, deterministic):
//   1. k_count_init : in-degree over dst (float atomics) + stream x0 into g_xa
//   2. k_scan       : single-pass decoupled-lookback exclusive scan -> ptr/cursor
//   3. k_scatter    : counting-sort edges into dst buckets, packed (src,norm) float2
//   4. k_prop(0)    : layer 1  x0(g_xa) -> x1(g_xb)
//   5. k_prop(1)    : layer 2  x1(g_xb) -> x2(g_xc)
//   6. k_prop3      : layer 3  reads g_xc, fuses mean: out = 0.25*(x0+x1+x2+x3)
//   7. k_tail       : re-zero degf + lookback flags for the next call
// prop layout: 8 lanes per node (chunk = lane&7 -> float4 of the 32-float row),
// 4 independent nodes per warp. No cross-lane reduction needed.
// NOTE: all x-buffer selection happens in DEVICE code (taking the address of a
// __device__ global in host code is UB — that was round 6's bug).
// edge_index arrives as int32 (JAX x64 disabled downgrades jnp.int64).

#define D       32
#define NMAX    300032
#define EMAX    5000064
#define SCAN_B  1024
#define NBMAX   512

__device__ float  g_xa[NMAX * D];        // x0
__device__ float  g_xb[NMAX * D];        // x1
__device__ float  g_xc[NMAX * D];        // x2
__device__ float  g_degf[NMAX];          // statically zero; re-zeroed by k_tail
__device__ int    g_ptr[NMAX + 1];
__device__ int    g_cursor[NMAX];
__device__ float2 g_edge[EMAX];          // .x = src (int bits), .y = norm
__device__ volatile int g_agg[NBMAX];
__device__ volatile int g_incl[NBMAX];
__device__ volatile int g_flag[NBMAX];   // 0/1/2; tail-zeroed

// ---- 1. degree count + x0 init (merged) ------------------------------------
__global__ void k_count_init(const int* __restrict__ ei, int E,
                             const float4* __restrict__ ue4,
                             const float4* __restrict__ ie4,
                             int nu8, int total8) {
    int t = blockIdx.x * blockDim.x + threadIdx.x;
    if (t < E) {
        int dd = ei[E + t];
        if (dd >= 0 && dd < NMAX) atomicAdd(&g_degf[dd], 1.0f);
    }
    if (t < total8)
        ((float4*)g_xa)[t] = (t < nu8) ? ue4[t] : ie4[t - nu8];
}

// ---- 2. single-pass scan (decoupled lookback) -------------------------------
__global__ void k_scan(int n, int E) {
    __shared__ int sh[SCAN_B];
    __shared__ int sh_prefix;
    int b = blockIdx.x, tid = threadIdx.x;
    int gid = b * SCAN_B + tid;
    int v = (gid < n) ? (int)g_degf[gid] : 0;
    sh[tid] = v;
    __syncthreads();
    for (int off = 1; off < SCAN_B; off <<= 1) {
        int t = (tid >= off) ? sh[tid - off] : 0;
        __syncthreads();
        sh[tid] += t;
        __syncthreads();
    }
    int total = sh[SCAN_B - 1];
    if (tid == 0) {
        g_agg[b] = total;
        __threadfence();
        g_flag[b] = 1;
        int sum = 0;
        for (int j = b - 1; j >= 0; --j) {
            int f;
            do { f = g_flag[j]; } while (f == 0);
            if (f == 2) { sum += g_incl[j]; break; }
            sum += g_agg[j];
        }
        sh_prefix = sum;
        g_incl[b] = sum + total;
        __threadfence();
        g_flag[b] = 2;
    }
    __syncthreads();
    int excl = sh_prefix + sh[tid] - v;
    if (gid < n) {
        g_ptr[gid]    = excl;
        g_cursor[gid] = excl;
    } else if (gid == n) {
        g_ptr[n] = E;
    }
}

// ---- 3. counting-sort scatter: one 8B (src, norm) store per edge -----------
__global__ void k_scatter(const int* __restrict__ ei, int E) {
    int e = blockIdx.x * blockDim.x + threadIdx.x;
    if (e >= E) return;
    int s  = ei[e];
    int dd = ei[E + e];
    if (s < 0 || s >= NMAX || dd < 0 || dd >= NMAX) return;
    int pos = atomicAdd(&g_cursor[dd], 1);
    float dp = g_degf[s] * g_degf[dd];
    float nm = (dp > 0.f) ? rsqrtf(dp) : 0.f;
    g_edge[pos] = make_float2(__int_as_float(s), nm);
}

// ---- bucket accumulate: 8 lanes own one node, float4 per lane --------------
__device__ __forceinline__ float4 bucket_sum(const float4* __restrict__ xin,
                                             int node, int chunk) {
    int j = g_ptr[node], end = g_ptr[node + 1];
    float ax = 0.f, ay = 0.f, az = 0.f, aw = 0.f;
    float bx = 0.f, by = 0.f, bz = 0.f, bw = 0.f;
    for (; j + 1 < end; j += 2) {
        float2 e0 = g_edge[j];
        float2 e1 = g_edge[j + 1];
        float4 v0 = xin[__float_as_int(e0.x) * 8 + chunk];
        float4 v1 = xin[__float_as_int(e1.x) * 8 + chunk];
        ax = fmaf(v0.x, e0.y, ax); ay = fmaf(v0.y, e0.y, ay);
        az = fmaf(v0.z, e0.y, az); aw = fmaf(v0.w, e0.y, aw);
        bx = fmaf(v1.x, e1.y, bx); by = fmaf(v1.y, e1.y, by);
        bz = fmaf(v1.z, e1.y, bz); bw = fmaf(v1.w, e1.y, bw);
    }
    if (j < end) {
        float2 e0 = g_edge[j];
        float4 v0 = xin[__float_as_int(e0.x) * 8 + chunk];
        ax = fmaf(v0.x, e0.y, ax); ay = fmaf(v0.y, e0.y, ay);
        az = fmaf(v0.z, e0.y, az); aw = fmaf(v0.w, e0.y, aw);
    }
    return make_float4(ax + bx, ay + by, az + bz, aw + bw);
}

// ---- 4/5. propagate layer: 4 nodes per warp, 8 lanes per node --------------
// sel 0: g_xa -> g_xb (layer 1);  sel 1: g_xb -> g_xc (layer 2)
__global__ void k_prop(int sel, int n) {
    int t = blockIdx.x * blockDim.x + threadIdx.x;
    int node  = t >> 3;          // 8 lanes per node
    int chunk = t & 7;
    if (node >= n) return;
    const float4* __restrict__ xin  = (const float4*)(sel ? g_xb : g_xa);
    float4*       __restrict__ xout = (float4*)(sel ? g_xc : g_xb);
    xout[node * 8 + chunk] = bucket_sum(xin, node, chunk);
}

// ---- 6. layer 3 + fused mean: out = 0.25*(x0+x1+x2+x3) ----------------------
__global__ void k_prop3(float4* __restrict__ out, int n) {
    int t = blockIdx.x * blockDim.x + threadIdx.x;
    int node  = t >> 3;
    int chunk = t & 7;
    if (node >= n) return;
    const float4* __restrict__ xin = (const float4*)g_xc;   // x2
    float4 a = bucket_sum(xin, node, chunk);                // x3
    int o = node * 8 + chunk;
    float4 v0 = ((const float4*)g_xa)[o];
    float4 v1 = ((const float4*)g_xb)[o];
    float4 v2 = xin[o];
    out[o] = make_float4(0.25f * (v0.x + v1.x + v2.x + a.x),
                         0.25f * (v0.y + v1.y + v2.y + a.y),
                         0.25f * (v0.z + v1.z + v2.z + a.z),
                         0.25f * (v0.w + v1.w + v2.w + a.w));
}

// ---- 7. reset state for the next call ---------------------------------------
__global__ void k_tail(int n) {
    int i = blockIdx.x * blockDim.x + threadIdx.x;
    if (i < n) g_degf[i] = 0.f;
    if (i < NBMAX) g_flag[i] = 0;
}

extern "C" void kernel_launch(void* const* d_in, const int* in_sizes, int n_in,
                              void* d_out, int out_size) {
    const int* ei = (const int*)d_in[0];   // edge_index: int32
    int iu = (n_in >= 5) ? 3 : 1;
    const float* ue = (const float*)d_in[iu];
    const float* ie = (const float*)d_in[iu + 1];
    int E       = in_sizes[0] / 2;
    int n_users = in_sizes[iu] / D;
    int n_items = in_sizes[iu + 1] / D;
    int n = n_users + n_items;
    float4* out4 = (float4*)d_out;

    const int TB = 256;
    int nu8 = n_users * (D / 4);
    int total8 = n * (D / 4);
    int gc = max(E, total8);

    k_count_init<<<(gc + TB - 1) / TB, TB>>>(ei, E, (const float4*)ue,
                                             (const float4*)ie, nu8, total8);
    int nb = (n + SCAN_B - 1) / SCAN_B;
    k_scan   <<<nb, SCAN_B>>>(n, E);
    k_scatter<<<(E + TB - 1) / TB, TB>>>(ei, E);

    int gp = (n * 8 + TB - 1) / TB;            // 8 lanes per node
    k_prop <<<gp, TB>>>(0, n);                 // x0 -> x1   [ncu slot #4]
    k_prop <<<gp, TB>>>(1, n);                 // x1 -> x2
    k_prop3<<<gp, TB>>>(out4, n);              // x2 -> x3, fused mean

    k_tail<<<(n + TB - 1) / TB, TB>>>(n);
}

// round 8
// speedup vs baseline: 1.8880x; 1.2655x over previous
#include <cuda_runtime.h>

// LightGCN on GB300 (sm_103a).
// Norm factorization: (deg_s*deg_d)^-1/2 = r[s]*r[d], r = deg^-1/2.
// Keep row-scaled embeddings y = r*x; propagation is an unweighted gather-sum:
//   s[d] = sum_{(s,d) in E} y[s];  y_next[d] = s*r[d]^2;  x_l[d] = s*r[d].
// Edge record is just the 4-byte src index. Per call:
//   1. k_count   : in-degree over dst (float atomics)
//   2. k_scan    : decoupled-lookback scan -> ptr/cursor; r[]; y0 = r*x0 -> g_xa
//   3. k_scatter : counting-sort src indices into dst buckets
//   4. k_prop(0) : y0(g_xa) -> y1(g_xb)     [ncu slot #4]
//   5. k_prop(1) : y1(g_xb) -> y2(g_xc)
//   6. k_prop3   : t = sum y2;  out = 0.25*(x0 + sq*y1 + sq*y2 + r*t), sq=sqrt(deg)
//   7. k_tail    : re-zero degf + lookback flags
// prop layout: 8 lanes per node (chunk=lane&7 -> float4 of row), 4 nodes/warp,
// unroll 4 (4 gathers in flight per lane). Buffer selection in device code only.
// edge_index arrives as int32 (JAX x64 disabled downgrades jnp.int64).

#define D       32
#define NMAX    300032
#define EMAX    5000064
#define SCAN_B  1024
#define NBMAX   512

__device__ float g_xa[NMAX * D];        // y0
__device__ float g_xb[NMAX * D];        // y1
__device__ float g_xc[NMAX * D];        // y2
__device__ float g_degf[NMAX];          // statically zero; re-zeroed by k_tail
__device__ float g_r[NMAX];             // deg^-1/2 (0 for deg==0)
__device__ int   g_ptr[NMAX + 1];
__device__ int   g_cursor[NMAX];
__device__ int   g_src[EMAX];           // bucketed src indices
__device__ volatile int g_agg[NBMAX];
__device__ volatile int g_incl[NBMAX];
__device__ volatile int g_flag[NBMAX];  // 0/1/2; tail-zeroed

// ---- 1. in-degree over dst ---------------------------------------------------
__global__ void k_count(const int* __restrict__ ei, int E) {
    int t = blockIdx.x * blockDim.x + threadIdx.x;
    if (t < E) {
        int dd = ei[E + t];
        if (dd >= 0 && dd < NMAX) atomicAdd(&g_degf[dd], 1.0f);
    }
}

// ---- 2. scan (decoupled lookback) + r[] + y0 init ------------------------------
__global__ void k_scan(int n, int E,
                       const float4* __restrict__ ue4,
                       const float4* __restrict__ ie4, int n_users) {
    __shared__ int sh[SCAN_B];
    __shared__ int sh_prefix;
    int b = blockIdx.x, tid = threadIdx.x;
    int gid = b * SCAN_B + tid;
    float dgf = (gid < n) ? g_degf[gid] : 0.f;
    int v = (int)dgf;
    sh[tid] = v;
    __syncthreads();
    for (int off = 1; off < SCAN_B; off <<= 1) {
        int t = (tid >= off) ? sh[tid - off] : 0;
        __syncthreads();
        sh[tid] += t;
        __syncthreads();
    }
    int total = sh[SCAN_B - 1];
    if (tid == 0) {
        g_agg[b] = total;
        __threadfence();
        g_flag[b] = 1;
        int sum = 0;
        for (int j = b - 1; j >= 0; --j) {
            int f;
            do { f = g_flag[j]; } while (f == 0);
            if (f == 2) { sum += g_incl[j]; break; }
            sum += g_agg[j];
        }
        sh_prefix = sum;
        g_incl[b] = sum + total;
        __threadfence();
        g_flag[b] = 2;
    }
    __syncthreads();
    int excl = sh_prefix + sh[tid] - v;
    if (gid < n) {
        g_ptr[gid]    = excl;
        g_cursor[gid] = excl;
        g_r[gid]      = (dgf > 0.f) ? rsqrtf(dgf) : 0.f;
    } else if (gid == n) {
        g_ptr[n] = E;
    }
    // y0 = r * x0 for this block's nodes
    int base = b * SCAN_B;
    int cnt = n - base;
    if (cnt > SCAN_B) cnt = SCAN_B;
    if (cnt > 0) {
        for (int idx = tid; idx < cnt * 8; idx += SCAN_B) {
            int node  = base + (idx >> 3);
            int chunk = idx & 7;
            float dg = g_degf[node];
            float r  = (dg > 0.f) ? rsqrtf(dg) : 0.f;
            float4 x = (node < n_users) ? ue4[node * 8 + chunk]
                                        : ie4[(node - n_users) * 8 + chunk];
            ((float4*)g_xa)[node * 8 + chunk] =
                make_float4(r * x.x, r * x.y, r * x.z, r * x.w);
        }
    }
}

// ---- 3. counting-sort scatter: one 4B src store per edge ----------------------
__global__ void k_scatter(const int* __restrict__ ei, int E) {
    int e = blockIdx.x * blockDim.x + threadIdx.x;
    if (e >= E) return;
    int s  = ei[e];
    int dd = ei[E + e];
    if (s < 0 || s >= NMAX || dd < 0 || dd >= NMAX) return;
    int pos = atomicAdd(&g_cursor[dd], 1);
    g_src[pos] = s;
}

// ---- bucket gather-sum: 8 lanes own one node, float4 per lane, unroll 4 -------
__device__ __forceinline__ float4 bucket_sum(const float4* __restrict__ xin,
                                             int i0, int end, int chunk) {
    float ax = 0.f, ay = 0.f, az = 0.f, aw = 0.f;
    float bx = 0.f, by = 0.f, bz = 0.f, bw = 0.f;
    float cx = 0.f, cy = 0.f, cz = 0.f, cw = 0.f;
    float dx = 0.f, dy = 0.f, dz = 0.f, dw = 0.f;
    int j = i0;
    for (; j + 3 < end; j += 4) {
        int s0 = g_src[j],     s1 = g_src[j + 1];
        int s2 = g_src[j + 2], s3 = g_src[j + 3];
        float4 v0 = xin[s0 * 8 + chunk];
        float4 v1 = xin[s1 * 8 + chunk];
        float4 v2 = xin[s2 * 8 + chunk];
        float4 v3 = xin[s3 * 8 + chunk];
        ax += v0.x; ay += v0.y; az += v0.z; aw += v0.w;
        bx += v1.x; by += v1.y; bz += v1.z; bw += v1.w;
        cx += v2.x; cy += v2.y; cz += v2.z; cw += v2.w;
        dx += v3.x; dy += v3.y; dz += v3.z; dw += v3.w;
    }
    for (; j < end; ++j) {
        float4 v0 = xin[g_src[j] * 8 + chunk];
        ax += v0.x; ay += v0.y; az += v0.z; aw += v0.w;
    }
    return make_float4((ax + bx) + (cx + dx), (ay + by) + (cy + dy),
                       (az + bz) + (cz + dz), (aw + bw) + (cw + dw));
}

// ---- 4/5. propagate: y_next = (sum y[src]) * r^2 -------------------------------
// sel 0: g_xa -> g_xb;  sel 1: g_xb -> g_xc
__global__ void k_prop(int sel, int n) {
    int t = blockIdx.x * blockDim.x + threadIdx.x;
    int node  = t >> 3;
    int chunk = t & 7;
    if (node >= n) return;
    const float4* __restrict__ xin  = (const float4*)(sel ? g_xb : g_xa);
    float4*       __restrict__ xout = (float4*)(sel ? g_xc : g_xb);
    int i0 = g_ptr[node], end = g_ptr[node + 1];
    float4 a = bucket_sum(xin, i0, end, chunk);
    float r  = g_r[node];
    float rr = r * r;
    xout[node * 8 + chunk] = make_float4(a.x * rr, a.y * rr, a.z * rr, a.w * rr);
}

// ---- 6. layer 3 + fused mean ----------------------------------------------------
// out = 0.25*(x0 + sq*y1 + sq*y2 + r*t), sq = sqrt(deg), t = sum y2[src]
__global__ void k_prop3(const float4* __restrict__ ue4,
                        const float4* __restrict__ ie4,
                        float4* __restrict__ out, int n_users, int n) {
    int t = blockIdx.x * blockDim.x + threadIdx.x;
    int node  = t >> 3;
    int chunk = t & 7;
    if (node >= n) return;
    const float4* __restrict__ xin = (const float4*)g_xc;   // y2
    int i0 = g_ptr[node], end = g_ptr[node + 1];
    float4 a = bucket_sum(xin, i0, end, chunk);              // t
    float r  = g_r[node];
    float dg = g_degf[node];
    float sq = (dg > 0.f) ? sqrtf(dg) : 0.f;
    int o = node * 8 + chunk;
    float4 x0 = (node < n_users) ? ue4[o] : ie4[(node - n_users) * 8 + chunk];
    float4 y1 = ((const float4*)g_xb)[o];
    float4 y2 = xin[o];
    out[o] = make_float4(0.25f * (x0.x + sq * (y1.x + y2.x) + r * a.x),
                         0.25f * (x0.y + sq * (y1.y + y2.y) + r * a.y),
                         0.25f * (x0.z + sq * (y1.z + y2.z) + r * a.z),
                         0.25f * (x0.w + sq * (y1.w + y2.w) + r * a.w));
}

// ---- 7. reset state for the next call --------------------------------------------
__global__ void k_tail(int n) {
    int i = blockIdx.x * blockDim.x + threadIdx.x;
    if (i < n) g_degf[i] = 0.f;
    if (i < NBMAX) g_flag[i] = 0;
}

extern "C" void kernel_launch(void* const* d_in, const int* in_sizes, int n_in,
                              void* d_out, int out_size) {
    const int* ei = (const int*)d_in[0];   // edge_index: int32
    int iu = (n_in >= 5) ? 3 : 1;
    const float* ue = (const float*)d_in[iu];
    const float* ie = (const float*)d_in[iu + 1];
    int E       = in_sizes[0] / 2;
    int n_users = in_sizes[iu] / D;
    int n_items = in_sizes[iu + 1] / D;
    int n = n_users + n_items;
    float4* out4 = (float4*)d_out;

    const int TB = 256;
    int nb = (n + SCAN_B - 1) / SCAN_B;

    k_count  <<<(E + TB - 1) / TB, TB>>>(ei, E);
    k_scan   <<<nb, SCAN_B>>>(n, E, (const float4*)ue, (const float4*)ie, n_users);
    k_scatter<<<(E + TB - 1) / TB, TB>>>(ei, E);

    int gp = (n * 8 + TB - 1) / TB;            // 8 lanes per node
    k_prop <<<gp, TB>>>(0, n);                 // y0 -> y1   [ncu slot #4]
    k_prop <<<gp, TB>>>(1, n);                 // y1 -> y2
    k_prop3<<<gp, TB>>>((const float4*)ue, (const float4*)ie, out4, n_users, n);

    k_tail<<<(n + TB - 1) / TB, TB>>>(n);
}

// round 9
// speedup vs baseline: 2.4032x; 1.2729x over previous
#include <cuda_runtime.h>
#include <cuda_fp16.h>

// LightGCN on GB300 (sm_103a).
// Norm factorization: (deg_s*deg_d)^-1/2 = r[s]*r[d], r = deg^-1/2.
// Row-scaled embeddings y = r*x stored in FP16 (64B rows): propagation is an
// unweighted gather-sum with fp32 accumulation:
//   t[d] = sum y[src];  y_next[d] = t*r[d]^2;  x_l[d] = t*r[d].
// Per call:
//   1. k_count   : in-degree over dst (float atomics)
//   2. k_scan    : decoupled-lookback scan -> ptr/cursor; r[]; y0=r*x0 (fp16)
//   3. k_scatter : counting-sort 4B src indices into dst buckets
//   4. k_prop(0) : y0 -> y1        [ncu slot #4]
//   5. k_prop(1) : y1 -> y2
//   6. k_prop3   : t = sum y2; out = 0.25*(x0 + sq*(y1+y2) + r*t), sq=sqrt(deg)
//   7. k_tail    : re-zero degf + lookback flags
// prop layout: 4 lanes per node (chunk=lane&3 -> uint4 of 8 halves), 8 nodes
// per warp, unroll 4. Buffer selection in device code only (R6 lesson).
// edge_index arrives as int32 (JAX x64 disabled downgrades jnp.int64).

#define D       32
#define NMAX    300032
#define EMAX    5000064
#define SCAN_B  1024
#define NBMAX   512

__device__ __half g_ya[NMAX * D];       // y0 (fp16)
__device__ __half g_yb[NMAX * D];       // y1
__device__ __half g_yc[NMAX * D];       // y2
__device__ float  g_degf[NMAX];         // statically zero; re-zeroed by k_tail
__device__ float  g_r[NMAX];            // deg^-1/2 (0 for deg==0)
__device__ int    g_ptr[NMAX + 1];
__device__ int    g_cursor[NMAX];
__device__ int    g_src[EMAX];          // bucketed src indices
__device__ volatile int g_agg[NBMAX];
__device__ volatile int g_incl[NBMAX];
__device__ volatile int g_flag[NBMAX];  // 0/1/2; tail-zeroed

__device__ __forceinline__ unsigned h2u(__half2 h) {
    return *reinterpret_cast<unsigned*>(&h);
}
__device__ __forceinline__ __half2 u2h(unsigned u) {
    return *reinterpret_cast<__half2*>(&u);
}
// unpack uint4 (8 halves) and add into 8 fp32 accumulators
__device__ __forceinline__ void acc8(float* a, uint4 v) {
    float2 f0 = __half22float2(u2h(v.x));
    float2 f1 = __half22float2(u2h(v.y));
    float2 f2 = __half22float2(u2h(v.z));
    float2 f3 = __half22float2(u2h(v.w));
    a[0] += f0.x; a[1] += f0.y; a[2] += f1.x; a[3] += f1.y;
    a[4] += f2.x; a[5] += f2.y; a[6] += f3.x; a[7] += f3.y;
}
// pack 8 fp32 (scaled) into uint4 of halves
__device__ __forceinline__ uint4 pack8(const float* a, float s) {
    uint4 o;
    o.x = h2u(__floats2half2_rn(a[0] * s, a[1] * s));
    o.y = h2u(__floats2half2_rn(a[2] * s, a[3] * s));
    o.z = h2u(__floats2half2_rn(a[4] * s, a[5] * s));
    o.w = h2u(__floats2half2_rn(a[6] * s, a[7] * s));
    return o;
}

// ---- 1. in-degree over dst ---------------------------------------------------
__global__ void k_count(const int* __restrict__ ei, int E) {
    int t = blockIdx.x * blockDim.x + threadIdx.x;
    if (t < E) {
        int dd = ei[E + t];
        if (dd >= 0 && dd < NMAX) atomicAdd(&g_degf[dd], 1.0f);
    }
}

// ---- 2. scan (decoupled lookback) + r[] + y0 init ------------------------------
__global__ void k_scan(int n, int E,
                       const float4* __restrict__ ue4,
                       const float4* __restrict__ ie4, int n_users) {
    __shared__ int sh[SCAN_B];
    __shared__ int sh_prefix;
    int b = blockIdx.x, tid = threadIdx.x;
    int gid = b * SCAN_B + tid;
    float dgf = (gid < n) ? g_degf[gid] : 0.f;
    int v = (int)dgf;
    sh[tid] = v;
    __syncthreads();
    for (int off = 1; off < SCAN_B; off <<= 1) {
        int t = (tid >= off) ? sh[tid - off] : 0;
        __syncthreads();
        sh[tid] += t;
        __syncthreads();
    }
    int total = sh[SCAN_B - 1];
    if (tid == 0) {
        g_agg[b] = total;
        __threadfence();
        g_flag[b] = 1;
        int sum = 0;
        for (int j = b - 1; j >= 0; --j) {
            int f;
            do { f = g_flag[j]; } while (f == 0);
            if (f == 2) { sum += g_incl[j]; break; }
            sum += g_agg[j];
        }
        sh_prefix = sum;
        g_incl[b] = sum + total;
        __threadfence();
        g_flag[b] = 2;
    }
    __syncthreads();
    int excl = sh_prefix + sh[tid] - v;
    if (gid < n) {
        g_ptr[gid]    = excl;
        g_cursor[gid] = excl;
        g_r[gid]      = (dgf > 0.f) ? rsqrtf(dgf) : 0.f;
    } else if (gid == n) {
        g_ptr[n] = E;
    }
    // y0 = r * x0 (fp16) for this block's nodes; 4 chunks per node
    int base = b * SCAN_B;
    int cnt = n - base;
    if (cnt > SCAN_B) cnt = SCAN_B;
    if (cnt > 0) {
        for (int idx = tid; idx < cnt * 4; idx += SCAN_B) {
            int node  = base + (idx >> 2);
            int chunk = idx & 3;
            float dg = g_degf[node];
            float r  = (dg > 0.f) ? rsqrtf(dg) : 0.f;
            int o8 = node * 8 + chunk * 2;
            float4 xa = (node < n_users) ? ue4[o8]     : ie4[o8 - n_users * 8];
            float4 xb = (node < n_users) ? ue4[o8 + 1] : ie4[o8 + 1 - n_users * 8];
            float a[8] = {xa.x, xa.y, xa.z, xa.w, xb.x, xb.y, xb.z, xb.w};
            ((uint4*)g_ya)[node * 4 + chunk] = pack8(a, r);
        }
    }
}

// ---- 3. counting-sort scatter: one 4B src store per edge ----------------------
__global__ void k_scatter(const int* __restrict__ ei, int E) {
    int e = blockIdx.x * blockDim.x + threadIdx.x;
    if (e >= E) return;
    int s  = ei[e];
    int dd = ei[E + e];
    if (s < 0 || s >= NMAX || dd < 0 || dd >= NMAX) return;
    int pos = atomicAdd(&g_cursor[dd], 1);
    g_src[pos] = s;
}

// ---- bucket gather-sum: 4 lanes own one node, 8 halves per lane, unroll 4 -----
__device__ __forceinline__ void bucket_sum_h(const uint4* __restrict__ Y,
                                             int i0, int end, int chunk,
                                             float* acc) {
    float a[8] = {0, 0, 0, 0, 0, 0, 0, 0};
    float b[8] = {0, 0, 0, 0, 0, 0, 0, 0};
    int j = i0;
    for (; j + 3 < end; j += 4) {
        int s0 = g_src[j],     s1 = g_src[j + 1];
        int s2 = g_src[j + 2], s3 = g_src[j + 3];
        uint4 v0 = Y[s0 * 4 + chunk];
        uint4 v1 = Y[s1 * 4 + chunk];
        uint4 v2 = Y[s2 * 4 + chunk];
        uint4 v3 = Y[s3 * 4 + chunk];
        acc8(a, v0); acc8(b, v1); acc8(a, v2); acc8(b, v3);
    }
    for (; j < end; ++j)
        acc8(a, Y[g_src[j] * 4 + chunk]);
    #pragma unroll
    for (int k = 0; k < 8; ++k) acc[k] = a[k] + b[k];
}

// ---- 4/5. propagate: y_next = (sum y[src]) * r^2 -------------------------------
// sel 0: g_ya -> g_yb;  sel 1: g_yb -> g_yc
__global__ void k_prop(int sel, int n) {
    int t = blockIdx.x * blockDim.x + threadIdx.x;
    int node  = t >> 2;
    int chunk = t & 3;
    if (node >= n) return;
    const uint4* __restrict__ Y  = (const uint4*)(sel ? g_yb : g_ya);
    uint4*       __restrict__ Yo = (uint4*)(sel ? g_yc : g_yb);
    float acc[8];
    bucket_sum_h(Y, g_ptr[node], g_ptr[node + 1], chunk, acc);
    float r  = g_r[node];
    Yo[node * 4 + chunk] = pack8(acc, r * r);
}

// ---- 6. layer 3 + fused mean ----------------------------------------------------
// out = 0.25*(x0 + sq*(y1+y2) + r*t), sq = sqrt(deg), t = sum y2[src]
__global__ void k_prop3(const float4* __restrict__ ue4,
                        const float4* __restrict__ ie4,
                        float4* __restrict__ out, int n_users, int n) {
    int t = blockIdx.x * blockDim.x + threadIdx.x;
    int node  = t >> 2;
    int chunk = t & 3;
    if (node >= n) return;
    const uint4* __restrict__ Y2 = (const uint4*)g_yc;
    float acc[8];
    bucket_sum_h(Y2, g_ptr[node], g_ptr[node + 1], chunk, acc);
    float r  = g_r[node];
    float dg = g_degf[node];
    float sq = (dg > 0.f) ? sqrtf(dg) : 0.f;
    // own y1 + y2 rows (fp16), x0 row (fp32 from inputs)
    float y1v[8] = {0, 0, 0, 0, 0, 0, 0, 0};
    float y2v[8] = {0, 0, 0, 0, 0, 0, 0, 0};
    acc8(y1v, ((const uint4*)g_yb)[node * 4 + chunk]);
    acc8(y2v, Y2[node * 4 + chunk]);
    int o8 = node * 8 + chunk * 2;
    float4 xa = (node < n_users) ? ue4[o8]     : ie4[o8 - n_users * 8];
    float4 xb = (node < n_users) ? ue4[o8 + 1] : ie4[o8 + 1 - n_users * 8];
    float x0v[8] = {xa.x, xa.y, xa.z, xa.w, xb.x, xb.y, xb.z, xb.w};
    float o[8];
    #pragma unroll
    for (int k = 0; k < 8; ++k)
        o[k] = 0.25f * (x0v[k] + sq * (y1v[k] + y2v[k]) + r * acc[k]);
    out[o8]     = make_float4(o[0], o[1], o[2], o[3]);
    out[o8 + 1] = make_float4(o[4], o[5], o[6], o[7]);
}

// ---- 7. reset state for the next call --------------------------------------------
__global__ void k_tail(int n) {
    int i = blockIdx.x * blockDim.x + threadIdx.x;
    if (i < n) g_degf[i] = 0.f;
    if (i < NBMAX) g_flag[i] = 0;
}

extern "C" void kernel_launch(void* const* d_in, const int* in_sizes, int n_in,
                              void* d_out, int out_size) {
    const int* ei = (const int*)d_in[0];   // edge_index: int32
    int iu = (n_in >= 5) ? 3 : 1;
    const float* ue = (const float*)d_in[iu];
    const float* ie = (const float*)d_in[iu + 1];
    int E       = in_sizes[0] / 2;
    int n_users = in_sizes[iu] / D;
    int n_items = in_sizes[iu + 1] / D;
    int n = n_users + n_items;
    float4* out4 = (float4*)d_out;

    const int TB = 256;
    int nb = (n + SCAN_B - 1) / SCAN_B;

    k_count  <<<(E + TB - 1) / TB, TB>>>(ei, E);
    k_scan   <<<nb, SCAN_B>>>(n, E, (const float4*)ue, (const float4*)ie, n_users);
    k_scatter<<<(E + TB - 1) / TB, TB>>>(ei, E);

    int gp = (n * 4 + TB - 1) / TB;            // 4 lanes per node
    k_prop <<<gp, TB>>>(0, n);                 // y0 -> y1   [ncu slot #4]
    k_prop <<<gp, TB>>>(1, n);                 // y1 -> y2
    k_prop3<<<gp, TB>>>((const float4*)ue, (const float4*)ie, out4, n_users, n);

    k_tail<<<(n + TB - 1) / TB, TB>>>(n);
}